// round 4
// baseline (speedup 1.0000x reference)
#include <cuda_runtime.h>
#include <cuda_fp16.h>
#include <stdint.h>

#define M_ROWS 16384
#define N_CODES 8192
#define KDIM 256
#define Q_ELEMS (M_ROWS * KDIM)

#define MT 128
#define NT 256
#define BK 32
#define STAGES 4
#define CHUNKS 24              // 3 passes * (256/32)

#define LDAB 80                // bytes per 32-half row in smem (40 halves, padded)
#define A_TILE_BYTES (128 * LDAB)   // 10240
#define B_TILE_BYTES (256 * LDAB)   // 20480
#define STAGE_BYTES (A_TILE_BYTES + B_TILE_BYTES)  // 30720
#define SMEM_EN 0
#define SMEM_STAGE0 1024
#define SMEM_TOTAL (SMEM_STAGE0 + STAGES * STAGE_BYTES)  // 123904

// ------------------------- persistent scratch -------------------------
__device__ unsigned long long g_best[M_ROWS];
__device__ float g_partial[M_ROWS];
__device__ float g_enorm[N_CODES];
__device__ __half g_zh[M_ROWS * KDIM];
__device__ __half g_zl[M_ROWS * KDIM];
__device__ __half g_eh[N_CODES * KDIM];
__device__ __half g_el[N_CODES * KDIM];

// ------------------------- helpers -------------------------
__device__ __forceinline__ uint32_t smem_u32(const void* p) {
    uint32_t a;
    asm("{ .reg .u64 t; cvta.to.shared.u64 t, %1; cvt.u32.u64 %0, t; }"
        : "=r"(a) : "l"(p));
    return a;
}
__device__ __forceinline__ void cp16(uint32_t dst, const void* src) {
    asm volatile("cp.async.cg.shared.global [%0], [%1], 16;" :: "r"(dst), "l"(src));
}
__device__ __forceinline__ void cp_commit() { asm volatile("cp.async.commit_group;"); }
__device__ __forceinline__ void cp_wait2() { asm volatile("cp.async.wait_group 2;" ::: "memory"); }
__device__ __forceinline__ void cp_wait1() { asm volatile("cp.async.wait_group 1;" ::: "memory"); }
__device__ __forceinline__ void cp_wait0() { asm volatile("cp.async.wait_group 0;" ::: "memory"); }

#define LDS128(r0, r1, r2, r3, addr) \
    asm volatile("ld.shared.v4.b32 {%0,%1,%2,%3}, [%4];" \
                 : "=r"(r0), "=r"(r1), "=r"(r2), "=r"(r3) : "r"(addr))

__device__ __forceinline__ unsigned fkey(float f) {
    unsigned u = __float_as_uint(f);
    return (u & 0x80000000u) ? ~u : (u | 0x80000000u);
}
__device__ __forceinline__ unsigned long long umin64(unsigned long long a,
                                                     unsigned long long b) {
    return a < b ? a : b;
}

// k-permutation within each 32-col chunk (identical for z & e, dot-invariant):
// orig k -> pos = t*8 + s*2 + p, where p=k&1, t=(k>>1)&3, s=(k>>3)&3.
// Thread t4 then reads its 8 fragment halves for a whole chunk at [t4*16B, +16B).
__device__ __forceinline__ int kperm_pos(int row, int k) {
    int kin = k & 31;
    int t = (kin >> 1) & 3;
    int sg = kin >> 3;
    return row * KDIM + (k & ~31) + t * 8 + sg * 2;
}

// ------------------------- prep kernels -------------------------
__global__ void split_z_kernel(const float* __restrict__ src) {
    int gid = blockIdx.x * 256 + threadIdx.x;  // 2,097,152 threads: one float2 each
    int row = gid >> 7;
    int k = (gid & 127) << 1;
    float2 v = ((const float2*)src)[gid];
    __half h0 = __float2half(v.x);
    __half l0 = __float2half(v.x - __half2float(h0));
    __half h1 = __float2half(v.y);
    __half l1 = __float2half(v.y - __half2float(h1));
    int pos = kperm_pos(row, k);
    *(__half2*)(g_zh + pos) = __halves2half2(h0, h1);
    *(__half2*)(g_zl + pos) = __halves2half2(l0, l1);
    if (gid < M_ROWS) g_best[gid] = ~0ull;
}

__global__ void split_e_kernel(const float* __restrict__ src) {
    int gid = blockIdx.x * 256 + threadIdx.x;  // 1,048,576 threads
    int row = gid >> 7;
    int k = (gid & 127) << 1;
    float2 v = ((const float2*)src)[gid];
    __half h0 = __float2half(v.x);
    __half l0 = __float2half(v.x - __half2float(h0));
    __half h1 = __float2half(v.y);
    __half l1 = __float2half(v.y - __half2float(h1));
    int pos = kperm_pos(row, k);
    *(__half2*)(g_eh + pos) = __halves2half2(h0, h1);
    *(__half2*)(g_el + pos) = __halves2half2(l0, l1);
}

__global__ void enorm_kernel(const float* __restrict__ emb) {
    int row = blockIdx.x * (blockDim.x >> 5) + (threadIdx.x >> 5);
    int lane = threadIdx.x & 31;
    if (row >= N_CODES) return;
    const float* e = emb + (size_t)row * KDIM;
    float s = 0.f;
#pragma unroll
    for (int c = lane; c < KDIM; c += 32) {
        float v = e[c];
        s = fmaf(v, v, s);
    }
#pragma unroll
    for (int o = 16; o; o >>= 1) s += __shfl_xor_sync(0xffffffffu, s, o);
    if (lane == 0) g_enorm[row] = s;
}

// ------------------------- GEMM + argmin -------------------------
// CTA tile 128(M) x 256(N); 512 threads = 16 warps in 4x4; warp tile 32x64.
// 3-pass fp16-split emulation of fp32 dot; distances d = ||e||^2 - 2*dot.
__global__ void __launch_bounds__(512, 1) vq_gemm_kernel() {
    extern __shared__ __align__(1024) char smem[];
    const uint32_t sb = smem_u32(smem);
    const int tid = threadIdx.x;
    const int bm = blockIdx.y * MT;
    const int bn = blockIdx.x * NT;

    if (tid < NT) ((float*)(smem + SMEM_EN))[tid] = g_enorm[bn + tid];

    const int w = tid >> 5;
    const int lane = tid & 31;
    const int g = lane >> 2;
    const int t4 = lane & 3;
    const int wm = w >> 2;  // 0..3
    const int wn = w & 3;   // 0..3

    float acc[2][8][4];
#pragma unroll
    for (int i = 0; i < 2; i++)
#pragma unroll
        for (int j = 0; j < 8; j++)
#pragma unroll
            for (int c = 0; c < 4; c++) acc[i][j][c] = 0.f;

    auto load_stage = [&](int s) {
        const int p = s >> 3;
        const int k0 = (s & 7) * BK;
        const __half* asrc = (p == 2) ? g_zl : g_zh;
        const __half* bsrc = (p == 1) ? g_el : g_eh;
        const uint32_t abase = sb + SMEM_STAGE0 + (uint32_t)(s & (STAGES - 1)) * STAGE_BYTES;
        const uint32_t bbase = abase + A_TILE_BYTES;
        {
            int row = tid >> 2, ch = tid & 3;
            cp16(abase + (uint32_t)(row * LDAB + ch * 16),
                 asrc + (size_t)(bm + row) * KDIM + k0 + ch * 8);
        }
#pragma unroll
        for (int it = 0; it < 2; it++) {
            int idx = tid + it * 512;
            int row = idx >> 2, ch = idx & 3;
            cp16(bbase + (uint32_t)(row * LDAB + ch * 16),
                 bsrc + (size_t)(bn + row) * KDIM + k0 + ch * 8);
        }
        cp_commit();
    };

    load_stage(0);
    load_stage(1);
    load_stage(2);

    for (int s = 0; s < CHUNKS; s++) {
        if (s < CHUNKS - 2) cp_wait2();
        else if (s == CHUNKS - 2) cp_wait1();
        else cp_wait0();
        __syncthreads();

        const uint32_t abase = sb + SMEM_STAGE0 + (uint32_t)(s & (STAGES - 1)) * STAGE_BYTES;
        const uint32_t bbase = abase + A_TILE_BYTES;

        uint32_t av[2][2][4];
#pragma unroll
        for (int i = 0; i < 2; i++)
#pragma unroll
            for (int gp = 0; gp < 2; gp++) {
                uint32_t addr = abase +
                    (uint32_t)((wm * 32 + i * 16 + gp * 8 + g) * LDAB + t4 * 16);
                LDS128(av[i][gp][0], av[i][gp][1], av[i][gp][2], av[i][gp][3], addr);
            }
        uint32_t bv[8][4];
#pragma unroll
        for (int j = 0; j < 8; j++) {
            uint32_t addr = bbase + (uint32_t)((wn * 64 + j * 8 + g) * LDAB + t4 * 16);
            LDS128(bv[j][0], bv[j][1], bv[j][2], bv[j][3], addr);
        }

#pragma unroll
        for (int j = 0; j < 8; j++)
#pragma unroll
            for (int i = 0; i < 2; i++)
#pragma unroll
                for (int ks = 0; ks < 2; ks++) {
                    asm("mma.sync.aligned.m16n8k16.row.col.f32.f16.f16.f32 "
                        "{%0,%1,%2,%3},{%4,%5,%6,%7},{%8,%9},{%0,%1,%2,%3};"
                        : "+f"(acc[i][j][0]), "+f"(acc[i][j][1]),
                          "+f"(acc[i][j][2]), "+f"(acc[i][j][3])
                        : "r"(av[i][0][2 * ks]), "r"(av[i][1][2 * ks]),
                          "r"(av[i][0][2 * ks + 1]), "r"(av[i][1][2 * ks + 1]),
                          "r"(bv[j][2 * ks]), "r"(bv[j][2 * ks + 1]));
                }

        if (s + 3 < CHUNKS) load_stage(s + 3);
    }

    // epilogue: distances + argmin keys, reduce across t4 lanes, atomicMin per row
    const float* en = (const float*)(smem + SMEM_EN);
#pragma unroll
    for (int i = 0; i < 2; i++)
#pragma unroll
        for (int gp = 0; gp < 2; gp++) {
            const int row = bm + wm * 32 + i * 16 + gp * 8 + g;
            unsigned long long best = ~0ull;
#pragma unroll
            for (int j = 0; j < 8; j++) {
                int n0 = wn * 64 + j * 8 + 2 * t4;
                float d0 = en[n0] - 2.0f * acc[i][j][gp * 2 + 0];
                float d1 = en[n0 + 1] - 2.0f * acc[i][j][gp * 2 + 1];
                unsigned long long k0 =
                    ((unsigned long long)fkey(d0) << 32) | (unsigned)(bn + n0);
                unsigned long long k1 =
                    ((unsigned long long)fkey(d1) << 32) | (unsigned)(bn + n0 + 1);
                best = umin64(best, umin64(k0, k1));
            }
            best = umin64(best, __shfl_xor_sync(0xffffffffu, best, 1));
            best = umin64(best, __shfl_xor_sync(0xffffffffu, best, 2));
            if (t4 == 0) atomicMin(&g_best[row], best);
        }
}

// ------------------------- gather + loss -------------------------
__global__ void gather_kernel(const float* __restrict__ z,
                              const float* __restrict__ emb,
                              float* __restrict__ out, int has_extra) {
    __shared__ float sw[8];
    const int tid = threadIdx.x;
    const int r = tid >> 6;
    const int c = tid & 63;
    const int row = blockIdx.x * 4 + r;
    unsigned long long key = g_best[row];
    int idx = (int)(key & 0xFFFFFFFFull);

    float4 q = ((const float4*)emb)[(size_t)idx * 64 + c];
    float4 zv = ((const float4*)z)[(size_t)row * 64 + c];
    ((float4*)out)[(size_t)row * 64 + c] = q;

    float dx = q.x - zv.x, dy = q.y - zv.y, dz = q.z - zv.z, dw = q.w - zv.w;
    float s = dx * dx + dy * dy + dz * dz + dw * dw;
#pragma unroll
    for (int o = 16; o; o >>= 1) s += __shfl_xor_sync(0xffffffffu, s, o);
    if ((tid & 31) == 0) sw[tid >> 5] = s;
    __syncthreads();
    if (c == 0) {
        float tot = sw[r * 2] + sw[r * 2 + 1];
        g_partial[row] = tot;
        if (has_extra) out[Q_ELEMS + 1 + row] = (float)idx;
    }
}

__global__ void finalize_kernel(float* __restrict__ out, int has_extra) {
    if (!has_extra) return;
    __shared__ float sh[256];
    int tid = threadIdx.x;
    float s = 0.f;
    for (int i = tid; i < M_ROWS; i += 256) s += g_partial[i];
    sh[tid] = s;
    __syncthreads();
#pragma unroll
    for (int o = 128; o; o >>= 1) {
        if (tid < o) sh[tid] += sh[tid + o];
        __syncthreads();
    }
    if (tid == 0) out[Q_ELEMS] = 1.25f * sh[0] / (float)Q_ELEMS;
}

// ------------------------- launcher -------------------------
extern "C" void kernel_launch(void* const* d_in, const int* in_sizes, int n_in,
                              void* d_out, int out_size) {
    const float* z;
    const float* emb;
    if (in_sizes[0] == M_ROWS * KDIM) {
        z = (const float*)d_in[0];
        emb = (const float*)d_in[1];
    } else {
        z = (const float*)d_in[1];
        emb = (const float*)d_in[0];
    }
    float* out = (float*)d_out;
    int has_extra = (out_size >= Q_ELEMS + 1 + M_ROWS) ? 1 : 0;

    cudaFuncSetAttribute(vq_gemm_kernel,
                         cudaFuncAttributeMaxDynamicSharedMemorySize, SMEM_TOTAL);

    split_z_kernel<<<Q_ELEMS / 2 / 256, 256>>>(z);          // also inits g_best
    split_e_kernel<<<N_CODES * KDIM / 2 / 256, 256>>>(emb);
    enorm_kernel<<<N_CODES / 8, 256>>>(emb);

    dim3 grid(N_CODES / NT, M_ROWS / MT);  // (32, 128)
    vq_gemm_kernel<<<grid, 512, SMEM_TOTAL>>>();

    gather_kernel<<<M_ROWS / 4, 256>>>(z, emb, out, has_extra);
    finalize_kernel<<<1, 256>>>(out, has_extra);
}

// round 5
// speedup vs baseline: 1.4031x; 1.4031x over previous
#include <cuda_runtime.h>
#include <cuda_fp16.h>
#include <stdint.h>

#define M_ROWS 16384
#define N_CODES 8192
#define KDIM 256
#define Q_ELEMS (M_ROWS * KDIM)

#define MT 128
#define NT 128
#define BK 32
#define STAGES 4
#define CHUNKS 24              // 3 passes * (256/32)

#define LDAB 80                // bytes per 32-half row (64B data + 16B pad)
#define A_TILE_BYTES (MT * LDAB)             // 10240
#define B_TILE_BYTES (NT * LDAB)             // 10240
#define STAGE_BYTES (A_TILE_BYTES + B_TILE_BYTES)  // 20480
#define SMEM_EN 0
#define SMEM_STAGE0 512
#define SMEM_TOTAL (SMEM_STAGE0 + STAGES * STAGE_BYTES)  // 82432

// ------------------------- persistent scratch -------------------------
__device__ unsigned long long g_best[M_ROWS];
__device__ float g_partial[M_ROWS];
__device__ float g_enorm[N_CODES];
__device__ __half g_zh[M_ROWS * KDIM];
__device__ __half g_zl[M_ROWS * KDIM];
__device__ __half g_eh[N_CODES * KDIM];
__device__ __half g_el[N_CODES * KDIM];

// ------------------------- helpers -------------------------
__device__ __forceinline__ uint32_t smem_u32(const void* p) {
    uint32_t a;
    asm("{ .reg .u64 t; cvta.to.shared.u64 t, %1; cvt.u32.u64 %0, t; }"
        : "=r"(a) : "l"(p));
    return a;
}
__device__ __forceinline__ void cp16(uint32_t dst, const void* src) {
    asm volatile("cp.async.cg.shared.global [%0], [%1], 16;" :: "r"(dst), "l"(src));
}
__device__ __forceinline__ void cp_commit() { asm volatile("cp.async.commit_group;"); }
__device__ __forceinline__ void cp_wait2() { asm volatile("cp.async.wait_group 2;" ::: "memory"); }
__device__ __forceinline__ void cp_wait1() { asm volatile("cp.async.wait_group 1;" ::: "memory"); }
__device__ __forceinline__ void cp_wait0() { asm volatile("cp.async.wait_group 0;" ::: "memory"); }

__device__ __forceinline__ unsigned fkey(float f) {
    unsigned u = __float_as_uint(f);
    return (u & 0x80000000u) ? ~u : (u | 0x80000000u);
}
__device__ __forceinline__ unsigned long long umin64(unsigned long long a,
                                                     unsigned long long b) {
    return a < b ? a : b;
}

// ------------------------- prep kernels -------------------------
__global__ void split_z_kernel(const float* __restrict__ src) {
    int gid = blockIdx.x * 256 + threadIdx.x;  // one float2 each
    float2 v = ((const float2*)src)[gid];
    __half h0 = __float2half(v.x);
    __half l0 = __float2half(v.x - __half2float(h0));
    __half h1 = __float2half(v.y);
    __half l1 = __float2half(v.y - __half2float(h1));
    *(__half2*)(g_zh + 2 * gid) = __halves2half2(h0, h1);
    *(__half2*)(g_zl + 2 * gid) = __halves2half2(l0, l1);
    if (gid < M_ROWS) g_best[gid] = ~0ull;
}

__global__ void split_e_kernel(const float* __restrict__ src) {
    int gid = blockIdx.x * 256 + threadIdx.x;
    float2 v = ((const float2*)src)[gid];
    __half h0 = __float2half(v.x);
    __half l0 = __float2half(v.x - __half2float(h0));
    __half h1 = __float2half(v.y);
    __half l1 = __float2half(v.y - __half2float(h1));
    *(__half2*)(g_eh + 2 * gid) = __halves2half2(h0, h1);
    *(__half2*)(g_el + 2 * gid) = __halves2half2(l0, l1);
}

__global__ void enorm_kernel(const float* __restrict__ emb) {
    int row = blockIdx.x * (blockDim.x >> 5) + (threadIdx.x >> 5);
    int lane = threadIdx.x & 31;
    if (row >= N_CODES) return;
    const float* e = emb + (size_t)row * KDIM;
    float s = 0.f;
#pragma unroll
    for (int c = lane; c < KDIM; c += 32) {
        float v = e[c];
        s = fmaf(v, v, s);
    }
#pragma unroll
    for (int o = 16; o; o >>= 1) s += __shfl_xor_sync(0xffffffffu, s, o);
    if (lane == 0) g_enorm[row] = s;
}

// ------------------------- GEMM + argmin -------------------------
// CTA 128x128, 256 threads = 8 warps (2 x 4); warp tile 64x32.
// fp16 m16n8k16, 3-pass split emulation (K_eff = 768).
__global__ void __launch_bounds__(256, 2) vq_gemm_kernel() {
    extern __shared__ __align__(256) char smem[];
    const uint32_t sb = smem_u32(smem);
    const int tid = threadIdx.x;
    const int bm = blockIdx.y * MT;
    const int bn = blockIdx.x * NT;

    if (tid < NT) ((float*)(smem + SMEM_EN))[tid] = g_enorm[bn + tid];

    const int w = tid >> 5;
    const int lane = tid & 31;
    const int g = lane >> 2;
    const int t4 = lane & 3;
    const int wm = w >> 2;  // 0..1 -> 64 rows
    const int wn = w & 3;   // 0..3 -> 32 cols

    float acc[4][4][4];
#pragma unroll
    for (int i = 0; i < 4; i++)
#pragma unroll
        for (int j = 0; j < 4; j++)
#pragma unroll
            for (int c = 0; c < 4; c++) acc[i][j][c] = 0.f;

    auto load_stage = [&](int s) {
        const int p = s >> 3;
        const int k0 = (s & 7) * BK;
        const __half* asrc = (p == 2) ? g_zl : g_zh;
        const __half* bsrc = (p == 1) ? g_el : g_eh;
        const uint32_t abase = sb + SMEM_STAGE0 + (uint32_t)(s & (STAGES - 1)) * STAGE_BYTES;
        const uint32_t bbase = abase + A_TILE_BYTES;
        // 128 rows * 64B = 4 x 16B per row; 512 cp16 over 256 threads
#pragma unroll
        for (int it = 0; it < 2; it++) {
            int idx = tid + it * 256;
            int row = idx >> 2, ch = idx & 3;
            cp16(abase + (uint32_t)(row * LDAB + ch * 16),
                 asrc + (size_t)(bm + row) * KDIM + k0 + ch * 8);
        }
#pragma unroll
        for (int it = 0; it < 2; it++) {
            int idx = tid + it * 256;
            int row = idx >> 2, ch = idx & 3;
            cp16(bbase + (uint32_t)(row * LDAB + ch * 16),
                 bsrc + (size_t)(bn + row) * KDIM + k0 + ch * 8);
        }
        cp_commit();
    };

    load_stage(0);
    load_stage(1);
    load_stage(2);

    for (int s = 0; s < CHUNKS; s++) {
        if (s < CHUNKS - 2) cp_wait2();
        else if (s == CHUNKS - 2) cp_wait1();
        else cp_wait0();
        __syncthreads();

        const uint32_t abase = sb + SMEM_STAGE0 + (uint32_t)(s & (STAGES - 1)) * STAGE_BYTES;
        const uint32_t bbase = abase + A_TILE_BYTES;
        const uint32_t arow = abase + (uint32_t)((wm * 64 + g) * LDAB + t4 * 4);
        const uint32_t brow = bbase + (uint32_t)((wn * 32 + g) * LDAB + t4 * 4);

#pragma unroll
        for (int ks = 0; ks < 2; ks++) {
            uint32_t a[4][4];
#pragma unroll
            for (int i = 0; i < 4; i++) {
                uint32_t ab = arow + (uint32_t)(i * 16 * LDAB + ks * 32);
                asm volatile("ld.shared.b32 %0, [%1];" : "=r"(a[i][0]) : "r"(ab));
                asm volatile("ld.shared.b32 %0, [%1];" : "=r"(a[i][1]) : "r"(ab + 8 * LDAB));
                asm volatile("ld.shared.b32 %0, [%1];" : "=r"(a[i][2]) : "r"(ab + 16));
                asm volatile("ld.shared.b32 %0, [%1];" : "=r"(a[i][3]) : "r"(ab + 8 * LDAB + 16));
            }
            uint32_t b[4][2];
#pragma unroll
            for (int j = 0; j < 4; j++) {
                uint32_t bb = brow + (uint32_t)(j * 8 * LDAB + ks * 32);
                asm volatile("ld.shared.b32 %0, [%1];" : "=r"(b[j][0]) : "r"(bb));
                asm volatile("ld.shared.b32 %0, [%1];" : "=r"(b[j][1]) : "r"(bb + 16));
            }
#pragma unroll
            for (int i = 0; i < 4; i++)
#pragma unroll
                for (int j = 0; j < 4; j++) {
                    asm("mma.sync.aligned.m16n8k16.row.col.f32.f16.f16.f32 "
                        "{%0,%1,%2,%3},{%4,%5,%6,%7},{%8,%9},{%0,%1,%2,%3};"
                        : "+f"(acc[i][j][0]), "+f"(acc[i][j][1]),
                          "+f"(acc[i][j][2]), "+f"(acc[i][j][3])
                        : "r"(a[i][0]), "r"(a[i][1]), "r"(a[i][2]), "r"(a[i][3]),
                          "r"(b[j][0]), "r"(b[j][1]));
                }
        }

        if (s + 3 < CHUNKS) load_stage(s + 3);
    }

    // epilogue: d = ||e||^2 - 2*dot; u64 (dist|idx) keys; min across t4; atomicMin
    const float* en = (const float*)(smem + SMEM_EN);
#pragma unroll
    for (int i = 0; i < 4; i++) {
        const int r0 = bm + wm * 64 + i * 16 + g;
        unsigned long long k0 = ~0ull, k1 = ~0ull;
#pragma unroll
        for (int j = 0; j < 4; j++) {
            int n0 = wn * 32 + j * 8 + 2 * t4;
            float d;
            unsigned long long key;
            d = en[n0] - 2.f * acc[i][j][0];
            key = ((unsigned long long)fkey(d) << 32) | (unsigned)(bn + n0);
            k0 = umin64(k0, key);
            d = en[n0 + 1] - 2.f * acc[i][j][1];
            key = ((unsigned long long)fkey(d) << 32) | (unsigned)(bn + n0 + 1);
            k0 = umin64(k0, key);
            d = en[n0] - 2.f * acc[i][j][2];
            key = ((unsigned long long)fkey(d) << 32) | (unsigned)(bn + n0);
            k1 = umin64(k1, key);
            d = en[n0 + 1] - 2.f * acc[i][j][3];
            key = ((unsigned long long)fkey(d) << 32) | (unsigned)(bn + n0 + 1);
            k1 = umin64(k1, key);
        }
        k0 = umin64(k0, __shfl_xor_sync(0xffffffffu, k0, 1));
        k0 = umin64(k0, __shfl_xor_sync(0xffffffffu, k0, 2));
        k1 = umin64(k1, __shfl_xor_sync(0xffffffffu, k1, 1));
        k1 = umin64(k1, __shfl_xor_sync(0xffffffffu, k1, 2));
        if (t4 == 0) {
            atomicMin(&g_best[r0], k0);
            atomicMin(&g_best[r0 + 8], k1);
        }
    }
}

// ------------------------- gather + loss -------------------------
__global__ void gather_kernel(const float* __restrict__ z,
                              const float* __restrict__ emb,
                              float* __restrict__ out, int has_extra) {
    __shared__ float sw[8];
    const int tid = threadIdx.x;
    const int r = tid >> 6;
    const int c = tid & 63;
    const int row = blockIdx.x * 4 + r;
    unsigned long long key = g_best[row];
    int idx = (int)(key & 0xFFFFFFFFull);

    float4 q = ((const float4*)emb)[(size_t)idx * 64 + c];
    float4 zv = ((const float4*)z)[(size_t)row * 64 + c];
    ((float4*)out)[(size_t)row * 64 + c] = q;

    float dx = q.x - zv.x, dy = q.y - zv.y, dz = q.z - zv.z, dw = q.w - zv.w;
    float s = dx * dx + dy * dy + dz * dz + dw * dw;
#pragma unroll
    for (int o = 16; o; o >>= 1) s += __shfl_xor_sync(0xffffffffu, s, o);
    if ((tid & 31) == 0) sw[tid >> 5] = s;
    __syncthreads();
    if (c == 0) {
        float tot = sw[r * 2] + sw[r * 2 + 1];
        g_partial[row] = tot;
        if (has_extra) out[Q_ELEMS + 1 + row] = (float)idx;
    }
}

__global__ void finalize_kernel(float* __restrict__ out, int has_extra) {
    if (!has_extra) return;
    __shared__ float sh[256];
    int tid = threadIdx.x;
    float s = 0.f;
    for (int i = tid; i < M_ROWS; i += 256) s += g_partial[i];
    sh[tid] = s;
    __syncthreads();
#pragma unroll
    for (int o = 128; o; o >>= 1) {
        if (tid < o) sh[tid] += sh[tid + o];
        __syncthreads();
    }
    if (tid == 0) out[Q_ELEMS] = 1.25f * sh[0] / (float)Q_ELEMS;
}

// ------------------------- launcher -------------------------
extern "C" void kernel_launch(void* const* d_in, const int* in_sizes, int n_in,
                              void* d_out, int out_size) {
    const float* z;
    const float* emb;
    if (in_sizes[0] == M_ROWS * KDIM) {
        z = (const float*)d_in[0];
        emb = (const float*)d_in[1];
    } else {
        z = (const float*)d_in[1];
        emb = (const float*)d_in[0];
    }
    float* out = (float*)d_out;
    int has_extra = (out_size >= Q_ELEMS + 1 + M_ROWS) ? 1 : 0;

    cudaFuncSetAttribute(vq_gemm_kernel,
                         cudaFuncAttributeMaxDynamicSharedMemorySize, SMEM_TOTAL);

    split_z_kernel<<<Q_ELEMS / 2 / 256, 256>>>(z);   // also inits g_best
    split_e_kernel<<<N_CODES * KDIM / 2 / 256, 256>>>(emb);
    enorm_kernel<<<N_CODES / 8, 256>>>(emb);

    dim3 grid(N_CODES / NT, M_ROWS / MT);  // (64, 128)
    vq_gemm_kernel<<<grid, 256, SMEM_TOTAL>>>();

    gather_kernel<<<M_ROWS / 4, 256>>>(z, emb, out, has_extra);
    finalize_kernel<<<1, 256>>>(out, has_extra);
}